// round 12
// baseline (speedup 1.0000x reference)
#include <cuda_runtime.h>
#include <cuda_fp16.h>
#include <cstdint>
#include <cstddef>

#define HH 128
#define WW 128
#define CCH 128
#define NB 8
#define C5T 640

typedef unsigned long long u64;

// ---------- scratch (__device__ globals: allocation-free) ----------
__device__ __half g_y[(size_t)NB * C5T * HH * WW];   // depthwise output (fp16), [b][q][n]
__device__ __half g_w4h[CCH * C5T];                  // w4 fp16, [o=128][q=640]
__device__ float2 g_wtab[64 * 85];                   // [cpair][cell*5+k] folded dw weights
__device__ float  g_bias3[C5T];                      // b1+b2+b3

// ---------- packed f32x2 helpers ----------
__device__ __forceinline__ u64 pack2(float x, float y) {
    u64 p; asm("mov.b64 %0, {%1, %2};" : "=l"(p) : "f"(x), "f"(y)); return p;
}
__device__ __forceinline__ void unpack2(u64 p, float& x, float& y) {
    asm("mov.b64 {%0, %1}, %2;" : "=f"(x), "=f"(y) : "l"(p));
}
__device__ __forceinline__ u64 ffma2(u64 a, u64 b, u64 c) {
    u64 d; asm("fma.rn.f32x2 %0, %1, %2, %3;" : "=l"(d) : "l"(a), "l"(b), "l"(c)); return d;
}
__device__ __forceinline__ u64 fadd2(u64 a, u64 b) {
    u64 d; asm("add.rn.f32x2 %0, %1, %2;" : "=l"(d) : "l"(a), "l"(b)); return d;
}

// ---------- prep: fold weights ----------
__global__ void prep_kernel(const float* __restrict__ w1, const float* __restrict__ b1,
                            const float* __restrict__ w2, const float* __restrict__ b2,
                            const float* __restrict__ w3, const float* __restrict__ b3,
                            const float* __restrict__ w4) {
    int stride = gridDim.x * blockDim.x;
    int tid = blockIdx.x * blockDim.x + threadIdx.x;
    for (int i = tid; i < CCH * C5T; i += stride) g_w4h[i] = __float2half(w4[i]);
    for (int q = tid; q < C5T; q += stride) g_bias3[q] = b1[q] + b2[q] + b3[q];
    const int NC[8] = {0,1,2,3,5,6,7,8};   // 3x3 taps excluding center
    for (int e = tid; e < 64 * 85; e += stride) {
        int cp = e / 85, rem = e % 85, cell = rem / 5, k = rem % 5;
        int q0 = k * CCH + cp * 2;
        float2 wv;
        if (cell == 0) {            // merged center: w1 + center of w2 + center of w3
            wv.x = w1[q0]     + w2[q0*9 + 4]     + w3[q0*9 + 4];
            wv.y = w1[q0 + 1] + w2[(q0+1)*9 + 4] + w3[(q0+1)*9 + 4];
        } else if (cell <= 8) {     // dil-8 taps
            int m = NC[cell - 1];
            wv.x = w2[q0*9 + m]; wv.y = w2[(q0+1)*9 + m];
        } else {                    // dil-12 taps
            int m = NC[cell - 9];
            wv.x = w3[q0*9 + m]; wv.y = w3[(q0+1)*9 + m];
        }
        g_wtab[e] = wv;
    }
}

// ---------- depthwise stencil (f32x2 packed math) ----------
// CTA: 32x32 spatial tile, one channel-pair, batch b. 256 threads:
// col = tid&31, 4 consecutive rows per thread. smem: padded x tile, halo 13.
__global__ __launch_bounds__(256) void dw_kernel(const float* __restrict__ x) {
    __shared__ u64 sx[58][58];
    __shared__ u64 sw[85];
    __shared__ u64 sb[5];

    int b  = blockIdx.z;
    int cp = blockIdx.y;
    int i0 = (blockIdx.x >> 2) * 32;
    int j0 = (blockIdx.x & 3) * 32;
    int tid = threadIdx.x;

    const float* x0 = x + ((size_t)b * CCH + 2 * cp) * (HH * WW);
    const float* x1 = x0 + HH * WW;

    for (int idx = tid; idx < 58 * 58; idx += 256) {
        int sr = idx / 58, sc = idx % 58;
        int gi = i0 - 13 + sr, gj = j0 - 13 + sc;
        float vx = 0.f, vy = 0.f;
        if (gi >= 0 && gi < HH && gj >= 0 && gj < WW) {
            vx = __ldg(x0 + gi * WW + gj);
            vy = __ldg(x1 + gi * WW + gj);
        }
        sx[sr][sc] = pack2(vx, vy);
    }
    if (tid < 85) {
        float2 w = g_wtab[cp * 85 + tid];
        sw[tid] = pack2(w.x, w.y);
    }
    if (tid < 5)
        sb[tid] = pack2(g_bias3[tid * CCH + 2 * cp], g_bias3[tid * CCH + 2 * cp + 1]);
    __syncthreads();

    int col = tid & 31;
    int rt  = (tid >> 5) * 4;     // local row base
    int gj  = j0 + col;
    int gi0 = i0 + rt;

    u64 acc[5][4];
#pragma unroll
    for (int k = 0; k < 5; k++)
#pragma unroll
        for (int p = 0; p < 4; p++) acc[k][p] = 0ull;  // +0.0f,+0.0f

    const int OY[17] = {0, -8,-8,-8, 0,0, 8,8,8, -12,-12,-12, 0,0, 12,12,12};
    const int OX[17] = {0, -8,0,8, -8,8, -8,0,8, -12,0,12, -12,12, -12,0,12};

#pragma unroll
    for (int cell = 0; cell < 17; cell++) {
        int gcj = gj + OX[cell];
        if (gcj < 0 || gcj >= WW) continue;       // conv-position column mask
        int cc = col + OX[cell] + 13;
        int rr = rt + OY[cell] + 13;
        u64 w0 = sw[cell*5+0], w1 = sw[cell*5+1], w2 = sw[cell*5+2];
        u64 w3 = sw[cell*5+3], w4 = sw[cell*5+4];

        u64 strip[6], lft[4], rgt[4];
#pragma unroll
        for (int s = 0; s < 6; s++) strip[s] = sx[rr - 1 + s][cc];
#pragma unroll
        for (int s = 0; s < 4; s++) { lft[s] = sx[rr + s][cc - 1]; rgt[s] = sx[rr + s][cc + 1]; }

#pragma unroll
        for (int p = 0; p < 4; p++) {
            int gci = gi0 + p + OY[cell];
            if (gci >= 0 && gci < HH) {           // conv-position row mask
                acc[0][p] = ffma2(w0, strip[p + 2], acc[0][p]);  // below  (i+1,j)
                acc[1][p] = ffma2(w1, strip[p],     acc[1][p]);  // above  (i-1,j)
                acc[2][p] = ffma2(w2, rgt[p],       acc[2][p]);  // right  (i,j+1)
                acc[3][p] = ffma2(w3, lft[p],       acc[3][p]);  // left   (i,j-1)
                acc[4][p] = ffma2(w4, strip[p + 1], acc[4][p]);  // center (i,j)
            }
        }
    }

    __half* yb = g_y + (size_t)b * C5T * (HH * WW);
#pragma unroll
    for (int k = 0; k < 5; k++) {
#pragma unroll
        for (int p = 0; p < 4; p++) {
            u64 r = fadd2(acc[k][p], sb[k]);
            float rx, ry; unpack2(r, rx, ry);
            size_t n = (size_t)(gi0 + p) * WW + gj;
            yb[(size_t)(k * CCH + 2 * cp) * (HH * WW) + n]     = __float2half(rx);
            yb[(size_t)(k * CCH + 2 * cp + 1) * (HH * WW) + n] = __float2half(ry);
        }
    }
}

// ---------- GEMM: out[b][o][n] = sum_q w4[o][q]*y[b][q][n] + b4[o] + x[b][o][n] ----------
// CTA 128x128, BK=32, 8 warps (2x4), warp 64x32 = 4x4 mma.m16n8k16.
// Bs: stride 128 halfs + XOR chunk swizzle -> conflict-free ldmatrix.trans.
#define CP16(dst, src) asm volatile("cp.async.cg.shared.global [%0], [%1], 16;\n" :: "r"(dst), "l"(src))
#define LDSM_X4(R, addr) asm volatile("ldmatrix.sync.aligned.m8n8.x4.shared.b16 {%0,%1,%2,%3}, [%4];\n" \
    : "=r"((R)[0]), "=r"((R)[1]), "=r"((R)[2]), "=r"((R)[3]) : "r"(addr))
#define LDSM_X2T(R, addr) asm volatile("ldmatrix.sync.aligned.m8n8.x2.trans.shared.b16 {%0,%1}, [%2];\n" \
    : "=r"((R)[0]), "=r"((R)[1]) : "r"(addr))
#define MMA16816(D, A, B) asm volatile( \
    "mma.sync.aligned.m16n8k16.row.col.f32.f16.f16.f32 {%0,%1,%2,%3},{%4,%5,%6,%7},{%8,%9},{%0,%1,%2,%3};\n" \
    : "+f"((D)[0]), "+f"((D)[1]), "+f"((D)[2]), "+f"((D)[3]) \
    : "r"((A)[0]), "r"((A)[1]), "r"((A)[2]), "r"((A)[3]), "r"((B)[0]), "r"((B)[1]))

__global__ __launch_bounds__(256) void gemm_kernel(const float* __restrict__ x,
                                                   const float* __restrict__ b4,
                                                   float* __restrict__ out) {
    __shared__ __align__(16) __half As[2][128][40];   // [stage][m][k] pad 8, stride 80B: conflict-free
    __shared__ __align__(16) __half Bs[2][32][128];   // [stage][k][n] swizzled chunks

    int b  = blockIdx.y;
    int n0 = blockIdx.x * 128;
    int tid = threadIdx.x;
    const __half* yb = g_y + (size_t)b * C5T * (HH * WW);

    auto loadA = [&](int s, int k0) {
#pragma unroll
        for (int u = 0; u < 2; u++) {
            int ch = tid + 256 * u;                 // 512 x 16B
            int row = ch >> 2, kc = (ch & 3) * 8;
            uint32_t dst = (uint32_t)__cvta_generic_to_shared(&As[s][row][kc]);
            CP16(dst, g_w4h + row * C5T + k0 + kc);
        }
    };
    auto loadB = [&](int s, int k0) {
#pragma unroll
        for (int u = 0; u < 2; u++) {
            int ch = tid + 256 * u;                 // 512 x 16B
            int row = ch >> 4, c = ch & 15;
            int sc = c ^ (row & 7);                 // XOR chunk swizzle
            uint32_t dst = (uint32_t)__cvta_generic_to_shared(&Bs[s][row][sc * 8]);
            CP16(dst, yb + (size_t)(k0 + row) * (HH * WW) + n0 + c * 8);
        }
    };

    loadA(0, 0); loadB(0, 0);
    asm volatile("cp.async.commit_group;\n");

    float acc[4][4][4];
#pragma unroll
    for (int mi = 0; mi < 4; mi++)
#pragma unroll
        for (int ni = 0; ni < 4; ni++)
#pragma unroll
            for (int r = 0; r < 4; r++) acc[mi][ni][r] = 0.f;

    int wid = tid >> 5, lane = tid & 31;
    int wm = wid >> 2;        // 0..1
    int wn = wid & 3;         // 0..3

    const int NKT = C5T / 32; // 20
    for (int kt = 0; kt < NKT; kt++) {
        int s = kt & 1;
        if (kt + 1 < NKT) {
            loadA((kt + 1) & 1, (kt + 1) * 32);
            loadB((kt + 1) & 1, (kt + 1) * 32);
            asm volatile("cp.async.commit_group;\n");
            asm volatile("cp.async.wait_group 1;\n");
        } else {
            asm volatile("cp.async.wait_group 0;\n");
        }
        __syncthreads();

#pragma unroll
        for (int kk = 0; kk < 32; kk += 16) {
            uint32_t a[4][4];
#pragma unroll
            for (int mi = 0; mi < 4; mi++) {
                int mrow = wm * 64 + mi * 16 + (lane & 15);
                uint32_t addr = (uint32_t)__cvta_generic_to_shared(
                    &As[s][mrow][kk + ((lane >> 4) << 3)]);
                LDSM_X4(a[mi], addr);
            }
#pragma unroll
            for (int ni = 0; ni < 4; ni++) {
                int r = kk + (lane & 15);
                int c0 = (wn * 4 + ni) ^ (r & 7);   // un-swizzle
                uint32_t bb[2];
                uint32_t addr = (uint32_t)__cvta_generic_to_shared(&Bs[s][r][c0 * 8]);
                LDSM_X2T(bb, addr);
#pragma unroll
                for (int mi = 0; mi < 4; mi++) MMA16816(acc[mi][ni], a[mi], bb);
            }
        }
        __syncthreads();
    }

    // epilogue: + b4[o] + x, fp32
    const float* xb = x + (size_t)b * CCH * (HH * WW);
    float* ob = out + (size_t)b * CCH * (HH * WW);
#pragma unroll
    for (int mi = 0; mi < 4; mi++) {
        int o0 = wm * 64 + mi * 16 + (lane >> 2);
        float bz0 = b4[o0], bz1 = b4[o0 + 8];
#pragma unroll
        for (int ni = 0; ni < 4; ni++) {
            int n = n0 + wn * 32 + ni * 8 + (lane & 3) * 2;
            const float2 xv0 = *(const float2*)(xb + (size_t)o0 * (HH * WW) + n);
            const float2 xv1 = *(const float2*)(xb + (size_t)(o0 + 8) * (HH * WW) + n);
            float2 r0, r1;
            r0.x = acc[mi][ni][0] + bz0 + xv0.x;
            r0.y = acc[mi][ni][1] + bz0 + xv0.y;
            r1.x = acc[mi][ni][2] + bz1 + xv1.x;
            r1.y = acc[mi][ni][3] + bz1 + xv1.y;
            *(float2*)(ob + (size_t)o0 * (HH * WW) + n) = r0;
            *(float2*)(ob + (size_t)(o0 + 8) * (HH * WW) + n) = r1;
        }
    }
}

// ---------- launch ----------
extern "C" void kernel_launch(void* const* d_in, const int* in_sizes, int n_in,
                              void* d_out, int out_size) {
    const float* x  = (const float*)d_in[0];
    const float* w1 = (const float*)d_in[1];
    const float* b1 = (const float*)d_in[2];
    const float* w2 = (const float*)d_in[3];
    const float* b2 = (const float*)d_in[4];
    const float* w3 = (const float*)d_in[5];
    const float* b3 = (const float*)d_in[6];
    const float* w4 = (const float*)d_in[7];
    const float* b4 = (const float*)d_in[8];
    float* out = (float*)d_out;

    prep_kernel<<<64, 256>>>(w1, b1, w2, b2, w3, b3, w4);
    dw_kernel<<<dim3(16, 64, NB), 256>>>(x);
    gemm_kernel<<<dim3(128, NB), 256>>>(x, b4, out);
}

// round 13
// speedup vs baseline: 1.0108x; 1.0108x over previous
#include <cuda_runtime.h>
#include <cuda_fp16.h>
#include <cstdint>
#include <cstddef>

#define HH 128
#define WW 128
#define CCH 128
#define NB 8
#define C5T 640

typedef unsigned long long u64;

// ---------- scratch (__device__ globals: allocation-free) ----------
__device__ __half g_y[(size_t)NB * C5T * HH * WW];   // depthwise output (fp16), [b][q][n]
__device__ __half g_w4h[CCH * C5T];                  // w4 fp16, [o=128][q=640]
__device__ float2 g_wtab[64 * 85];                   // [cpair][cell*5+k] folded dw weights
__device__ float  g_bias3[C5T];                      // b1+b2+b3

// ---------- packed f32x2 helpers ----------
__device__ __forceinline__ u64 pack2(float x, float y) {
    u64 p; asm("mov.b64 %0, {%1, %2};" : "=l"(p) : "f"(x), "f"(y)); return p;
}
__device__ __forceinline__ void unpack2(u64 p, float& x, float& y) {
    asm("mov.b64 {%0, %1}, %2;" : "=f"(x), "=f"(y) : "l"(p));
}
__device__ __forceinline__ u64 ffma2(u64 a, u64 b, u64 c) {
    u64 d; asm("fma.rn.f32x2 %0, %1, %2, %3;" : "=l"(d) : "l"(a), "l"(b), "l"(c)); return d;
}
__device__ __forceinline__ u64 fadd2(u64 a, u64 b) {
    u64 d; asm("add.rn.f32x2 %0, %1, %2;" : "=l"(d) : "l"(a), "l"(b)); return d;
}

// ---------- prep: fold weights ----------
__global__ void prep_kernel(const float* __restrict__ w1, const float* __restrict__ b1,
                            const float* __restrict__ w2, const float* __restrict__ b2,
                            const float* __restrict__ w3, const float* __restrict__ b3,
                            const float* __restrict__ w4) {
    int stride = gridDim.x * blockDim.x;
    int tid = blockIdx.x * blockDim.x + threadIdx.x;
    for (int i = tid; i < CCH * C5T; i += stride) g_w4h[i] = __float2half(w4[i]);
    for (int q = tid; q < C5T; q += stride) g_bias3[q] = b1[q] + b2[q] + b3[q];
    const int NC[8] = {0,1,2,3,5,6,7,8};   // 3x3 taps excluding center
    for (int e = tid; e < 64 * 85; e += stride) {
        int cp = e / 85, rem = e % 85, cell = rem / 5, k = rem % 5;
        int q0 = k * CCH + cp * 2;
        float2 wv;
        if (cell == 0) {            // merged center: w1 + center of w2 + center of w3
            wv.x = w1[q0]     + w2[q0*9 + 4]     + w3[q0*9 + 4];
            wv.y = w1[q0 + 1] + w2[(q0+1)*9 + 4] + w3[(q0+1)*9 + 4];
        } else if (cell <= 8) {     // dil-8 taps
            int m = NC[cell - 1];
            wv.x = w2[q0*9 + m]; wv.y = w2[(q0+1)*9 + m];
        } else {                    // dil-12 taps
            int m = NC[cell - 9];
            wv.x = w3[q0*9 + m]; wv.y = w3[(q0+1)*9 + m];
        }
        g_wtab[e] = wv;
    }
}

// ---------- depthwise stencil (f32x2 packed math) ----------
// CTA: 32x32 spatial tile, one channel-pair, batch b. 256 threads:
// col = tid&31, 4 consecutive rows per thread. smem: padded x tile, halo 13.
__global__ __launch_bounds__(256) void dw_kernel(const float* __restrict__ x) {
    __shared__ u64 sx[58][58];
    __shared__ u64 sw[85];
    __shared__ u64 sb[5];

    int b  = blockIdx.z;
    int cp = blockIdx.y;
    int i0 = (blockIdx.x >> 2) * 32;
    int j0 = (blockIdx.x & 3) * 32;
    int tid = threadIdx.x;

    const float* x0 = x + ((size_t)b * CCH + 2 * cp) * (HH * WW);
    const float* x1 = x0 + HH * WW;

    for (int idx = tid; idx < 58 * 58; idx += 256) {
        int sr = idx / 58, sc = idx % 58;
        int gi = i0 - 13 + sr, gj = j0 - 13 + sc;
        float vx = 0.f, vy = 0.f;
        if (gi >= 0 && gi < HH && gj >= 0 && gj < WW) {
            vx = __ldg(x0 + gi * WW + gj);
            vy = __ldg(x1 + gi * WW + gj);
        }
        sx[sr][sc] = pack2(vx, vy);
    }
    if (tid < 85) {
        float2 w = g_wtab[cp * 85 + tid];
        sw[tid] = pack2(w.x, w.y);
    }
    if (tid < 5)
        sb[tid] = pack2(g_bias3[tid * CCH + 2 * cp], g_bias3[tid * CCH + 2 * cp + 1]);
    __syncthreads();

    int col = tid & 31;
    int rt  = (tid >> 5) * 4;     // local row base
    int gj  = j0 + col;
    int gi0 = i0 + rt;

    u64 acc[5][4];
#pragma unroll
    for (int k = 0; k < 5; k++)
#pragma unroll
        for (int p = 0; p < 4; p++) acc[k][p] = 0ull;  // +0.0f,+0.0f

    const int OY[17] = {0, -8,-8,-8, 0,0, 8,8,8, -12,-12,-12, 0,0, 12,12,12};
    const int OX[17] = {0, -8,0,8, -8,8, -8,0,8, -12,0,12, -12,12, -12,0,12};

#pragma unroll
    for (int cell = 0; cell < 17; cell++) {
        int gcj = gj + OX[cell];
        if (gcj < 0 || gcj >= WW) continue;       // conv-position column mask
        int cc = col + OX[cell] + 13;
        int rr = rt + OY[cell] + 13;
        u64 w0 = sw[cell*5+0], w1 = sw[cell*5+1], w2 = sw[cell*5+2];
        u64 w3 = sw[cell*5+3], w4 = sw[cell*5+4];

        u64 strip[6], lft[4], rgt[4];
#pragma unroll
        for (int s = 0; s < 6; s++) strip[s] = sx[rr - 1 + s][cc];
#pragma unroll
        for (int s = 0; s < 4; s++) { lft[s] = sx[rr + s][cc - 1]; rgt[s] = sx[rr + s][cc + 1]; }

#pragma unroll
        for (int p = 0; p < 4; p++) {
            int gci = gi0 + p + OY[cell];
            if (gci >= 0 && gci < HH) {           // conv-position row mask
                acc[0][p] = ffma2(w0, strip[p + 2], acc[0][p]);  // below  (i+1,j)
                acc[1][p] = ffma2(w1, strip[p],     acc[1][p]);  // above  (i-1,j)
                acc[2][p] = ffma2(w2, rgt[p],       acc[2][p]);  // right  (i,j+1)
                acc[3][p] = ffma2(w3, lft[p],       acc[3][p]);  // left   (i,j-1)
                acc[4][p] = ffma2(w4, strip[p + 1], acc[4][p]);  // center (i,j)
            }
        }
    }

    __half* yb = g_y + (size_t)b * C5T * (HH * WW);
#pragma unroll
    for (int k = 0; k < 5; k++) {
#pragma unroll
        for (int p = 0; p < 4; p++) {
            u64 r = fadd2(acc[k][p], sb[k]);
            float rx, ry; unpack2(r, rx, ry);
            size_t n = (size_t)(gi0 + p) * WW + gj;
            yb[(size_t)(k * CCH + 2 * cp) * (HH * WW) + n]     = __float2half(rx);
            yb[(size_t)(k * CCH + 2 * cp + 1) * (HH * WW) + n] = __float2half(ry);
        }
    }
}

// ---------- GEMM: out[b][o][n] = sum_q w4[o][q]*y[b][q][n] + b4[o] + x[b][o][n] ----------
// CTA 128x128, BK=32, 8 warps (2x4), warp 64x32 = 4x4 mma.m16n8k16.
// Bs: stride 128 halfs + XOR chunk swizzle -> conflict-free ldmatrix.trans.
#define CP16(dst, src) asm volatile("cp.async.cg.shared.global [%0], [%1], 16;\n" :: "r"(dst), "l"(src))
#define LDSM_X4(R, addr) asm volatile("ldmatrix.sync.aligned.m8n8.x4.shared.b16 {%0,%1,%2,%3}, [%4];\n" \
    : "=r"((R)[0]), "=r"((R)[1]), "=r"((R)[2]), "=r"((R)[3]) : "r"(addr))
#define LDSM_X2T(R, addr) asm volatile("ldmatrix.sync.aligned.m8n8.x2.trans.shared.b16 {%0,%1}, [%2];\n" \
    : "=r"((R)[0]), "=r"((R)[1]) : "r"(addr))
#define MMA16816(D, A, B) asm volatile( \
    "mma.sync.aligned.m16n8k16.row.col.f32.f16.f16.f32 {%0,%1,%2,%3},{%4,%5,%6,%7},{%8,%9},{%0,%1,%2,%3};\n" \
    : "+f"((D)[0]), "+f"((D)[1]), "+f"((D)[2]), "+f"((D)[3]) \
    : "r"((A)[0]), "r"((A)[1]), "r"((A)[2]), "r"((A)[3]), "r"((B)[0]), "r"((B)[1]))

__global__ __launch_bounds__(256) void gemm_kernel(const float* __restrict__ x,
                                                   const float* __restrict__ b4,
                                                   float* __restrict__ out) {
    __shared__ __align__(16) __half As[2][128][40];   // [stage][m][k] pad 8, stride 80B: conflict-free
    __shared__ __align__(16) __half Bs[2][32][128];   // [stage][k][n] swizzled chunks

    int b  = blockIdx.y;
    int n0 = blockIdx.x * 128;
    int tid = threadIdx.x;
    const __half* yb = g_y + (size_t)b * C5T * (HH * WW);

    auto loadA = [&](int s, int k0) {
#pragma unroll
        for (int u = 0; u < 2; u++) {
            int ch = tid + 256 * u;                 // 512 x 16B
            int row = ch >> 2, kc = (ch & 3) * 8;
            uint32_t dst = (uint32_t)__cvta_generic_to_shared(&As[s][row][kc]);
            CP16(dst, g_w4h + row * C5T + k0 + kc);
        }
    };
    auto loadB = [&](int s, int k0) {
#pragma unroll
        for (int u = 0; u < 2; u++) {
            int ch = tid + 256 * u;                 // 512 x 16B
            int row = ch >> 4, c = ch & 15;
            int sc = c ^ (row & 7);                 // XOR chunk swizzle
            uint32_t dst = (uint32_t)__cvta_generic_to_shared(&Bs[s][row][sc * 8]);
            CP16(dst, yb + (size_t)(k0 + row) * (HH * WW) + n0 + c * 8);
        }
    };

    loadA(0, 0); loadB(0, 0);
    asm volatile("cp.async.commit_group;\n");

    float acc[4][4][4];
#pragma unroll
    for (int mi = 0; mi < 4; mi++)
#pragma unroll
        for (int ni = 0; ni < 4; ni++)
#pragma unroll
            for (int r = 0; r < 4; r++) acc[mi][ni][r] = 0.f;

    int wid = tid >> 5, lane = tid & 31;
    int wm = wid >> 2;        // 0..1
    int wn = wid & 3;         // 0..3

    const int NKT = C5T / 32; // 20
    for (int kt = 0; kt < NKT; kt++) {
        int s = kt & 1;
        if (kt + 1 < NKT) {
            loadA((kt + 1) & 1, (kt + 1) * 32);
            loadB((kt + 1) & 1, (kt + 1) * 32);
            asm volatile("cp.async.commit_group;\n");
            asm volatile("cp.async.wait_group 1;\n");
        } else {
            asm volatile("cp.async.wait_group 0;\n");
        }
        __syncthreads();

#pragma unroll
        for (int kk = 0; kk < 32; kk += 16) {
            uint32_t a[4][4];
#pragma unroll
            for (int mi = 0; mi < 4; mi++) {
                int mrow = wm * 64 + mi * 16 + (lane & 15);
                uint32_t addr = (uint32_t)__cvta_generic_to_shared(
                    &As[s][mrow][kk + ((lane >> 4) << 3)]);
                LDSM_X4(a[mi], addr);
            }
#pragma unroll
            for (int ni = 0; ni < 4; ni++) {
                int r = kk + (lane & 15);
                int c0 = (wn * 4 + ni) ^ (r & 7);   // un-swizzle
                uint32_t bb[2];
                uint32_t addr = (uint32_t)__cvta_generic_to_shared(&Bs[s][r][c0 * 8]);
                LDSM_X2T(bb, addr);
#pragma unroll
                for (int mi = 0; mi < 4; mi++) MMA16816(acc[mi][ni], a[mi], bb);
            }
        }
        __syncthreads();
    }

    // epilogue: + b4[o] + x, fp32
    const float* xb = x + (size_t)b * CCH * (HH * WW);
    float* ob = out + (size_t)b * CCH * (HH * WW);
#pragma unroll
    for (int mi = 0; mi < 4; mi++) {
        int o0 = wm * 64 + mi * 16 + (lane >> 2);
        float bz0 = b4[o0], bz1 = b4[o0 + 8];
#pragma unroll
        for (int ni = 0; ni < 4; ni++) {
            int n = n0 + wn * 32 + ni * 8 + (lane & 3) * 2;
            const float2 xv0 = *(const float2*)(xb + (size_t)o0 * (HH * WW) + n);
            const float2 xv1 = *(const float2*)(xb + (size_t)(o0 + 8) * (HH * WW) + n);
            float2 r0, r1;
            r0.x = acc[mi][ni][0] + bz0 + xv0.x;
            r0.y = acc[mi][ni][1] + bz0 + xv0.y;
            r1.x = acc[mi][ni][2] + bz1 + xv1.x;
            r1.y = acc[mi][ni][3] + bz1 + xv1.y;
            *(float2*)(ob + (size_t)o0 * (HH * WW) + n) = r0;
            *(float2*)(ob + (size_t)(o0 + 8) * (HH * WW) + n) = r1;
        }
    }
}

// ---------- launch ----------
extern "C" void kernel_launch(void* const* d_in, const int* in_sizes, int n_in,
                              void* d_out, int out_size) {
    const float* x  = (const float*)d_in[0];
    const float* w1 = (const float*)d_in[1];
    const float* b1 = (const float*)d_in[2];
    const float* w2 = (const float*)d_in[3];
    const float* b2 = (const float*)d_in[4];
    const float* w3 = (const float*)d_in[5];
    const float* b3 = (const float*)d_in[6];
    const float* w4 = (const float*)d_in[7];
    const float* b4 = (const float*)d_in[8];
    float* out = (float*)d_out;

    prep_kernel<<<64, 256>>>(w1, b1, w2, b2, w3, b3, w4);
    dw_kernel<<<dim3(16, 64, NB), 256>>>(x);
    gemm_kernel<<<dim3(128, NB), 256>>>(x, b4, out);
}

// round 14
// speedup vs baseline: 1.0125x; 1.0017x over previous
#include <cuda_runtime.h>
#include <cuda_fp16.h>
#include <cstdint>
#include <cstddef>

#define HH 128
#define WW 128
#define CCH 128
#define NB 8
#define C5T 640

typedef unsigned long long u64;

// ---------- scratch (__device__ globals: allocation-free) ----------
__device__ __half g_y[(size_t)NB * C5T * HH * WW];   // depthwise output (fp16), [b][q][n]
__device__ __half g_w4h[CCH * C5T];                  // w4 fp16, [o=128][q=640]
__device__ float2 g_wtab[64 * 85];                   // [cpair][cell*5+k] folded dw weights
__device__ float  g_bias3[C5T];                      // b1+b2+b3

// ---------- packed f32x2 helpers ----------
__device__ __forceinline__ u64 pack2(float x, float y) {
    u64 p; asm("mov.b64 %0, {%1, %2};" : "=l"(p) : "f"(x), "f"(y)); return p;
}
__device__ __forceinline__ void unpack2(u64 p, float& x, float& y) {
    asm("mov.b64 {%0, %1}, %2;" : "=f"(x), "=f"(y) : "l"(p));
}
__device__ __forceinline__ u64 ffma2(u64 a, u64 b, u64 c) {
    u64 d; asm("fma.rn.f32x2 %0, %1, %2, %3;" : "=l"(d) : "l"(a), "l"(b), "l"(c)); return d;
}
__device__ __forceinline__ u64 fadd2(u64 a, u64 b) {
    u64 d; asm("add.rn.f32x2 %0, %1, %2;" : "=l"(d) : "l"(a), "l"(b)); return d;
}

// ---------- prep: fold weights ----------
__global__ void prep_kernel(const float* __restrict__ w1, const float* __restrict__ b1,
                            const float* __restrict__ w2, const float* __restrict__ b2,
                            const float* __restrict__ w3, const float* __restrict__ b3,
                            const float* __restrict__ w4) {
    int stride = gridDim.x * blockDim.x;
    int tid = blockIdx.x * blockDim.x + threadIdx.x;
    for (int i = tid; i < CCH * C5T; i += stride) g_w4h[i] = __float2half(w4[i]);
    for (int q = tid; q < C5T; q += stride) g_bias3[q] = b1[q] + b2[q] + b3[q];
    const int NC[8] = {0,1,2,3,5,6,7,8};   // 3x3 taps excluding center
    for (int e = tid; e < 64 * 85; e += stride) {
        int cp = e / 85, rem = e % 85, cell = rem / 5, k = rem % 5;
        int q0 = k * CCH + cp * 2;
        float2 wv;
        if (cell == 0) {            // merged center: w1 + center of w2 + center of w3
            wv.x = w1[q0]     + w2[q0*9 + 4]     + w3[q0*9 + 4];
            wv.y = w1[q0 + 1] + w2[(q0+1)*9 + 4] + w3[(q0+1)*9 + 4];
        } else if (cell <= 8) {     // dil-8 taps
            int m = NC[cell - 1];
            wv.x = w2[q0*9 + m]; wv.y = w2[(q0+1)*9 + m];
        } else {                    // dil-12 taps
            int m = NC[cell - 9];
            wv.x = w3[q0*9 + m]; wv.y = w3[(q0+1)*9 + m];
        }
        g_wtab[e] = wv;
    }
}

// ---------- depthwise stencil (f32x2 packed math) ----------
// CTA: 32x32 spatial tile, one channel-pair, batch b. 256 threads:
// col = tid&31, 4 consecutive rows per thread. smem: padded x tile, halo 13.
__global__ __launch_bounds__(256) void dw_kernel(const float* __restrict__ x) {
    __shared__ u64 sx[58][58];
    __shared__ u64 sw[85];
    __shared__ u64 sb[5];

    int b  = blockIdx.z;
    int cp = blockIdx.y;
    int i0 = (blockIdx.x >> 2) * 32;
    int j0 = (blockIdx.x & 3) * 32;
    int tid = threadIdx.x;

    const float* x0 = x + ((size_t)b * CCH + 2 * cp) * (HH * WW);
    const float* x1 = x0 + HH * WW;

    for (int idx = tid; idx < 58 * 58; idx += 256) {
        int sr = idx / 58, sc = idx % 58;
        int gi = i0 - 13 + sr, gj = j0 - 13 + sc;
        float vx = 0.f, vy = 0.f;
        if (gi >= 0 && gi < HH && gj >= 0 && gj < WW) {
            vx = __ldg(x0 + gi * WW + gj);
            vy = __ldg(x1 + gi * WW + gj);
        }
        sx[sr][sc] = pack2(vx, vy);
    }
    if (tid < 85) {
        float2 w = g_wtab[cp * 85 + tid];
        sw[tid] = pack2(w.x, w.y);
    }
    if (tid < 5)
        sb[tid] = pack2(g_bias3[tid * CCH + 2 * cp], g_bias3[tid * CCH + 2 * cp + 1]);
    __syncthreads();

    int col = tid & 31;
    int rt  = (tid >> 5) * 4;     // local row base
    int gj  = j0 + col;
    int gi0 = i0 + rt;

    u64 acc[5][4];
#pragma unroll
    for (int k = 0; k < 5; k++)
#pragma unroll
        for (int p = 0; p < 4; p++) acc[k][p] = 0ull;  // +0.0f,+0.0f

    const int OY[17] = {0, -8,-8,-8, 0,0, 8,8,8, -12,-12,-12, 0,0, 12,12,12};
    const int OX[17] = {0, -8,0,8, -8,8, -8,0,8, -12,0,12, -12,12, -12,0,12};

#pragma unroll
    for (int cell = 0; cell < 17; cell++) {
        int gcj = gj + OX[cell];
        if (gcj < 0 || gcj >= WW) continue;       // conv-position column mask
        int cc = col + OX[cell] + 13;
        int rr = rt + OY[cell] + 13;
        u64 w0 = sw[cell*5+0], w1 = sw[cell*5+1], w2 = sw[cell*5+2];
        u64 w3 = sw[cell*5+3], w4 = sw[cell*5+4];

        u64 strip[6], lft[4], rgt[4];
#pragma unroll
        for (int s = 0; s < 6; s++) strip[s] = sx[rr - 1 + s][cc];
#pragma unroll
        for (int s = 0; s < 4; s++) { lft[s] = sx[rr + s][cc - 1]; rgt[s] = sx[rr + s][cc + 1]; }

#pragma unroll
        for (int p = 0; p < 4; p++) {
            int gci = gi0 + p + OY[cell];
            if (gci >= 0 && gci < HH) {           // conv-position row mask
                acc[0][p] = ffma2(w0, strip[p + 2], acc[0][p]);  // below  (i+1,j)
                acc[1][p] = ffma2(w1, strip[p],     acc[1][p]);  // above  (i-1,j)
                acc[2][p] = ffma2(w2, rgt[p],       acc[2][p]);  // right  (i,j+1)
                acc[3][p] = ffma2(w3, lft[p],       acc[3][p]);  // left   (i,j-1)
                acc[4][p] = ffma2(w4, strip[p + 1], acc[4][p]);  // center (i,j)
            }
        }
    }

    __half* yb = g_y + (size_t)b * C5T * (HH * WW);
#pragma unroll
    for (int k = 0; k < 5; k++) {
#pragma unroll
        for (int p = 0; p < 4; p++) {
            u64 r = fadd2(acc[k][p], sb[k]);
            float rx, ry; unpack2(r, rx, ry);
            size_t n = (size_t)(gi0 + p) * WW + gj;
            yb[(size_t)(k * CCH + 2 * cp) * (HH * WW) + n]     = __float2half(rx);
            yb[(size_t)(k * CCH + 2 * cp + 1) * (HH * WW) + n] = __float2half(ry);
        }
    }
}

// ---------- GEMM: out[b][o][n] = sum_q w4[o][q]*y[b][q][n] + b4[o] + x[b][o][n] ----------
// CTA 128x128, BK=32, 8 warps (2x4), warp 64x32 = 4x4 mma.m16n8k16.
// Bs: stride 128 halfs + XOR chunk swizzle -> conflict-free ldmatrix.trans.
#define CP16(dst, src) asm volatile("cp.async.cg.shared.global [%0], [%1], 16;\n" :: "r"(dst), "l"(src))
#define LDSM_X4(R, addr) asm volatile("ldmatrix.sync.aligned.m8n8.x4.shared.b16 {%0,%1,%2,%3}, [%4];\n" \
    : "=r"((R)[0]), "=r"((R)[1]), "=r"((R)[2]), "=r"((R)[3]) : "r"(addr))
#define LDSM_X2T(R, addr) asm volatile("ldmatrix.sync.aligned.m8n8.x2.trans.shared.b16 {%0,%1}, [%2];\n" \
    : "=r"((R)[0]), "=r"((R)[1]) : "r"(addr))
#define MMA16816(D, A, B) asm volatile( \
    "mma.sync.aligned.m16n8k16.row.col.f32.f16.f16.f32 {%0,%1,%2,%3},{%4,%5,%6,%7},{%8,%9},{%0,%1,%2,%3};\n" \
    : "+f"((D)[0]), "+f"((D)[1]), "+f"((D)[2]), "+f"((D)[3]) \
    : "r"((A)[0]), "r"((A)[1]), "r"((A)[2]), "r"((A)[3]), "r"((B)[0]), "r"((B)[1]))

__global__ __launch_bounds__(256) void gemm_kernel(const float* __restrict__ x,
                                                   const float* __restrict__ b4,
                                                   float* __restrict__ out) {
    __shared__ __align__(16) __half As[2][128][40];   // [stage][m][k] pad 8, stride 80B: conflict-free
    __shared__ __align__(16) __half Bs[2][32][128];   // [stage][k][n] swizzled chunks

    int b  = blockIdx.y;
    int n0 = blockIdx.x * 128;
    int tid = threadIdx.x;
    const __half* yb = g_y + (size_t)b * C5T * (HH * WW);

    auto loadA = [&](int s, int k0) {
#pragma unroll
        for (int u = 0; u < 2; u++) {
            int ch = tid + 256 * u;                 // 512 x 16B
            int row = ch >> 2, kc = (ch & 3) * 8;
            uint32_t dst = (uint32_t)__cvta_generic_to_shared(&As[s][row][kc]);
            CP16(dst, g_w4h + row * C5T + k0 + kc);
        }
    };
    auto loadB = [&](int s, int k0) {
#pragma unroll
        for (int u = 0; u < 2; u++) {
            int ch = tid + 256 * u;                 // 512 x 16B
            int row = ch >> 4, c = ch & 15;
            int sc = c ^ (row & 7);                 // XOR chunk swizzle
            uint32_t dst = (uint32_t)__cvta_generic_to_shared(&Bs[s][row][sc * 8]);
            CP16(dst, yb + (size_t)(k0 + row) * (HH * WW) + n0 + c * 8);
        }
    };

    loadA(0, 0); loadB(0, 0);
    asm volatile("cp.async.commit_group;\n");

    float acc[4][4][4];
#pragma unroll
    for (int mi = 0; mi < 4; mi++)
#pragma unroll
        for (int ni = 0; ni < 4; ni++)
#pragma unroll
            for (int r = 0; r < 4; r++) acc[mi][ni][r] = 0.f;

    int wid = tid >> 5, lane = tid & 31;
    int wm = wid >> 2;        // 0..1
    int wn = wid & 3;         // 0..3

    const int NKT = C5T / 32; // 20
    for (int kt = 0; kt < NKT; kt++) {
        int s = kt & 1;
        if (kt + 1 < NKT) {
            loadA((kt + 1) & 1, (kt + 1) * 32);
            loadB((kt + 1) & 1, (kt + 1) * 32);
            asm volatile("cp.async.commit_group;\n");
            asm volatile("cp.async.wait_group 1;\n");
        } else {
            asm volatile("cp.async.wait_group 0;\n");
        }
        __syncthreads();

#pragma unroll
        for (int kk = 0; kk < 32; kk += 16) {
            uint32_t a[4][4];
#pragma unroll
            for (int mi = 0; mi < 4; mi++) {
                int mrow = wm * 64 + mi * 16 + (lane & 15);
                uint32_t addr = (uint32_t)__cvta_generic_to_shared(
                    &As[s][mrow][kk + ((lane >> 4) << 3)]);
                LDSM_X4(a[mi], addr);
            }
#pragma unroll
            for (int ni = 0; ni < 4; ni++) {
                int r = kk + (lane & 15);
                int c0 = (wn * 4 + ni) ^ (r & 7);   // un-swizzle
                uint32_t bb[2];
                uint32_t addr = (uint32_t)__cvta_generic_to_shared(&Bs[s][r][c0 * 8]);
                LDSM_X2T(bb, addr);
#pragma unroll
                for (int mi = 0; mi < 4; mi++) MMA16816(acc[mi][ni], a[mi], bb);
            }
        }
        __syncthreads();
    }

    // epilogue: + b4[o] + x, fp32
    const float* xb = x + (size_t)b * CCH * (HH * WW);
    float* ob = out + (size_t)b * CCH * (HH * WW);
#pragma unroll
    for (int mi = 0; mi < 4; mi++) {
        int o0 = wm * 64 + mi * 16 + (lane >> 2);
        float bz0 = b4[o0], bz1 = b4[o0 + 8];
#pragma unroll
        for (int ni = 0; ni < 4; ni++) {
            int n = n0 + wn * 32 + ni * 8 + (lane & 3) * 2;
            const float2 xv0 = *(const float2*)(xb + (size_t)o0 * (HH * WW) + n);
            const float2 xv1 = *(const float2*)(xb + (size_t)(o0 + 8) * (HH * WW) + n);
            float2 r0, r1;
            r0.x = acc[mi][ni][0] + bz0 + xv0.x;
            r0.y = acc[mi][ni][1] + bz0 + xv0.y;
            r1.x = acc[mi][ni][2] + bz1 + xv1.x;
            r1.y = acc[mi][ni][3] + bz1 + xv1.y;
            *(float2*)(ob + (size_t)o0 * (HH * WW) + n) = r0;
            *(float2*)(ob + (size_t)(o0 + 8) * (HH * WW) + n) = r1;
        }
    }
}

// ---------- launch ----------
extern "C" void kernel_launch(void* const* d_in, const int* in_sizes, int n_in,
                              void* d_out, int out_size) {
    const float* x  = (const float*)d_in[0];
    const float* w1 = (const float*)d_in[1];
    const float* b1 = (const float*)d_in[2];
    const float* w2 = (const float*)d_in[3];
    const float* b2 = (const float*)d_in[4];
    const float* w3 = (const float*)d_in[5];
    const float* b3 = (const float*)d_in[6];
    const float* w4 = (const float*)d_in[7];
    const float* b4 = (const float*)d_in[8];
    float* out = (float*)d_out;

    prep_kernel<<<64, 256>>>(w1, b1, w2, b2, w3, b3, w4);
    dw_kernel<<<dim3(16, 64, NB), 256>>>(x);
    gemm_kernel<<<dim3(128, NB), 256>>>(x, b4, out);
}

// round 15
// speedup vs baseline: 1.0126x; 1.0001x over previous
#include <cuda_runtime.h>
#include <cuda_fp16.h>
#include <cstdint>
#include <cstddef>

#define HH 128
#define WW 128
#define CCH 128
#define NB 8
#define C5T 640

typedef unsigned long long u64;

// ---------- scratch (__device__ globals: allocation-free) ----------
__device__ __half g_y[(size_t)NB * C5T * HH * WW];   // depthwise output (fp16), [b][q][n]
__device__ __half g_w4h[CCH * C5T];                  // w4 fp16, [o=128][q=640]
__device__ float2 g_wtab[64 * 85];                   // [cpair][cell*5+k] folded dw weights
__device__ float  g_bias3[C5T];                      // b1+b2+b3

// ---------- packed f32x2 helpers ----------
__device__ __forceinline__ u64 pack2(float x, float y) {
    u64 p; asm("mov.b64 %0, {%1, %2};" : "=l"(p) : "f"(x), "f"(y)); return p;
}
__device__ __forceinline__ void unpack2(u64 p, float& x, float& y) {
    asm("mov.b64 {%0, %1}, %2;" : "=f"(x), "=f"(y) : "l"(p));
}
__device__ __forceinline__ u64 ffma2(u64 a, u64 b, u64 c) {
    u64 d; asm("fma.rn.f32x2 %0, %1, %2, %3;" : "=l"(d) : "l"(a), "l"(b), "l"(c)); return d;
}
__device__ __forceinline__ u64 fadd2(u64 a, u64 b) {
    u64 d; asm("add.rn.f32x2 %0, %1, %2;" : "=l"(d) : "l"(a), "l"(b)); return d;
}

// ---------- prep: fold weights ----------
__global__ void prep_kernel(const float* __restrict__ w1, const float* __restrict__ b1,
                            const float* __restrict__ w2, const float* __restrict__ b2,
                            const float* __restrict__ w3, const float* __restrict__ b3,
                            const float* __restrict__ w4) {
    int stride = gridDim.x * blockDim.x;
    int tid = blockIdx.x * blockDim.x + threadIdx.x;
    for (int i = tid; i < CCH * C5T; i += stride) g_w4h[i] = __float2half(w4[i]);
    for (int q = tid; q < C5T; q += stride) g_bias3[q] = b1[q] + b2[q] + b3[q];
    const int NC[8] = {0,1,2,3,5,6,7,8};   // 3x3 taps excluding center
    for (int e = tid; e < 64 * 85; e += stride) {
        int cp = e / 85, rem = e % 85, cell = rem / 5, k = rem % 5;
        int q0 = k * CCH + cp * 2;
        float2 wv;
        if (cell == 0) {            // merged center: w1 + center of w2 + center of w3
            wv.x = w1[q0]     + w2[q0*9 + 4]     + w3[q0*9 + 4];
            wv.y = w1[q0 + 1] + w2[(q0+1)*9 + 4] + w3[(q0+1)*9 + 4];
        } else if (cell <= 8) {     // dil-8 taps
            int m = NC[cell - 1];
            wv.x = w2[q0*9 + m]; wv.y = w2[(q0+1)*9 + m];
        } else {                    // dil-12 taps
            int m = NC[cell - 9];
            wv.x = w3[q0*9 + m]; wv.y = w3[(q0+1)*9 + m];
        }
        g_wtab[e] = wv;
    }
}

// ---------- depthwise stencil (f32x2 packed math) ----------
// CTA: 32x32 spatial tile, one channel-pair, batch b. 256 threads:
// col = tid&31, 4 consecutive rows per thread. smem: padded x tile, halo 13.
__global__ __launch_bounds__(256) void dw_kernel(const float* __restrict__ x) {
    __shared__ u64 sx[58][58];
    __shared__ u64 sw[85];
    __shared__ u64 sb[5];

    int b  = blockIdx.z;
    int cp = blockIdx.y;
    int i0 = (blockIdx.x >> 2) * 32;
    int j0 = (blockIdx.x & 3) * 32;
    int tid = threadIdx.x;

    const float* x0 = x + ((size_t)b * CCH + 2 * cp) * (HH * WW);
    const float* x1 = x0 + HH * WW;

    for (int idx = tid; idx < 58 * 58; idx += 256) {
        int sr = idx / 58, sc = idx % 58;
        int gi = i0 - 13 + sr, gj = j0 - 13 + sc;
        float vx = 0.f, vy = 0.f;
        if (gi >= 0 && gi < HH && gj >= 0 && gj < WW) {
            vx = __ldg(x0 + gi * WW + gj);
            vy = __ldg(x1 + gi * WW + gj);
        }
        sx[sr][sc] = pack2(vx, vy);
    }
    if (tid < 85) {
        float2 w = g_wtab[cp * 85 + tid];
        sw[tid] = pack2(w.x, w.y);
    }
    if (tid < 5)
        sb[tid] = pack2(g_bias3[tid * CCH + 2 * cp], g_bias3[tid * CCH + 2 * cp + 1]);
    __syncthreads();

    int col = tid & 31;
    int rt  = (tid >> 5) * 4;     // local row base
    int gj  = j0 + col;
    int gi0 = i0 + rt;

    u64 acc[5][4];
#pragma unroll
    for (int k = 0; k < 5; k++)
#pragma unroll
        for (int p = 0; p < 4; p++) acc[k][p] = 0ull;  // +0.0f,+0.0f

    const int OY[17] = {0, -8,-8,-8, 0,0, 8,8,8, -12,-12,-12, 0,0, 12,12,12};
    const int OX[17] = {0, -8,0,8, -8,8, -8,0,8, -12,0,12, -12,12, -12,0,12};

#pragma unroll
    for (int cell = 0; cell < 17; cell++) {
        int gcj = gj + OX[cell];
        if (gcj < 0 || gcj >= WW) continue;       // conv-position column mask
        int cc = col + OX[cell] + 13;
        int rr = rt + OY[cell] + 13;
        u64 w0 = sw[cell*5+0], w1 = sw[cell*5+1], w2 = sw[cell*5+2];
        u64 w3 = sw[cell*5+3], w4 = sw[cell*5+4];

        u64 strip[6], lft[4], rgt[4];
#pragma unroll
        for (int s = 0; s < 6; s++) strip[s] = sx[rr - 1 + s][cc];
#pragma unroll
        for (int s = 0; s < 4; s++) { lft[s] = sx[rr + s][cc - 1]; rgt[s] = sx[rr + s][cc + 1]; }

#pragma unroll
        for (int p = 0; p < 4; p++) {
            int gci = gi0 + p + OY[cell];
            if (gci >= 0 && gci < HH) {           // conv-position row mask
                acc[0][p] = ffma2(w0, strip[p + 2], acc[0][p]);  // below  (i+1,j)
                acc[1][p] = ffma2(w1, strip[p],     acc[1][p]);  // above  (i-1,j)
                acc[2][p] = ffma2(w2, rgt[p],       acc[2][p]);  // right  (i,j+1)
                acc[3][p] = ffma2(w3, lft[p],       acc[3][p]);  // left   (i,j-1)
                acc[4][p] = ffma2(w4, strip[p + 1], acc[4][p]);  // center (i,j)
            }
        }
    }

    __half* yb = g_y + (size_t)b * C5T * (HH * WW);
#pragma unroll
    for (int k = 0; k < 5; k++) {
#pragma unroll
        for (int p = 0; p < 4; p++) {
            u64 r = fadd2(acc[k][p], sb[k]);
            float rx, ry; unpack2(r, rx, ry);
            size_t n = (size_t)(gi0 + p) * WW + gj;
            yb[(size_t)(k * CCH + 2 * cp) * (HH * WW) + n]     = __float2half(rx);
            yb[(size_t)(k * CCH + 2 * cp + 1) * (HH * WW) + n] = __float2half(ry);
        }
    }
}

// ---------- GEMM: out[b][o][n] = sum_q w4[o][q]*y[b][q][n] + b4[o] + x[b][o][n] ----------
// CTA 128x128, BK=32, 8 warps (2x4), warp 64x32 = 4x4 mma.m16n8k16.
// Bs: stride 128 halfs + XOR chunk swizzle -> conflict-free ldmatrix.trans.
#define CP16(dst, src) asm volatile("cp.async.cg.shared.global [%0], [%1], 16;\n" :: "r"(dst), "l"(src))
#define LDSM_X4(R, addr) asm volatile("ldmatrix.sync.aligned.m8n8.x4.shared.b16 {%0,%1,%2,%3}, [%4];\n" \
    : "=r"((R)[0]), "=r"((R)[1]), "=r"((R)[2]), "=r"((R)[3]) : "r"(addr))
#define LDSM_X2T(R, addr) asm volatile("ldmatrix.sync.aligned.m8n8.x2.trans.shared.b16 {%0,%1}, [%2];\n" \
    : "=r"((R)[0]), "=r"((R)[1]) : "r"(addr))
#define MMA16816(D, A, B) asm volatile( \
    "mma.sync.aligned.m16n8k16.row.col.f32.f16.f16.f32 {%0,%1,%2,%3},{%4,%5,%6,%7},{%8,%9},{%0,%1,%2,%3};\n" \
    : "+f"((D)[0]), "+f"((D)[1]), "+f"((D)[2]), "+f"((D)[3]) \
    : "r"((A)[0]), "r"((A)[1]), "r"((A)[2]), "r"((A)[3]), "r"((B)[0]), "r"((B)[1]))

__global__ __launch_bounds__(256) void gemm_kernel(const float* __restrict__ x,
                                                   const float* __restrict__ b4,
                                                   float* __restrict__ out) {
    __shared__ __align__(16) __half As[2][128][40];   // [stage][m][k] pad 8, stride 80B: conflict-free
    __shared__ __align__(16) __half Bs[2][32][128];   // [stage][k][n] swizzled chunks

    int b  = blockIdx.y;
    int n0 = blockIdx.x * 128;
    int tid = threadIdx.x;
    const __half* yb = g_y + (size_t)b * C5T * (HH * WW);

    auto loadA = [&](int s, int k0) {
#pragma unroll
        for (int u = 0; u < 2; u++) {
            int ch = tid + 256 * u;                 // 512 x 16B
            int row = ch >> 2, kc = (ch & 3) * 8;
            uint32_t dst = (uint32_t)__cvta_generic_to_shared(&As[s][row][kc]);
            CP16(dst, g_w4h + row * C5T + k0 + kc);
        }
    };
    auto loadB = [&](int s, int k0) {
#pragma unroll
        for (int u = 0; u < 2; u++) {
            int ch = tid + 256 * u;                 // 512 x 16B
            int row = ch >> 4, c = ch & 15;
            int sc = c ^ (row & 7);                 // XOR chunk swizzle
            uint32_t dst = (uint32_t)__cvta_generic_to_shared(&Bs[s][row][sc * 8]);
            CP16(dst, yb + (size_t)(k0 + row) * (HH * WW) + n0 + c * 8);
        }
    };

    loadA(0, 0); loadB(0, 0);
    asm volatile("cp.async.commit_group;\n");

    float acc[4][4][4];
#pragma unroll
    for (int mi = 0; mi < 4; mi++)
#pragma unroll
        for (int ni = 0; ni < 4; ni++)
#pragma unroll
            for (int r = 0; r < 4; r++) acc[mi][ni][r] = 0.f;

    int wid = tid >> 5, lane = tid & 31;
    int wm = wid >> 2;        // 0..1
    int wn = wid & 3;         // 0..3

    const int NKT = C5T / 32; // 20
    for (int kt = 0; kt < NKT; kt++) {
        int s = kt & 1;
        if (kt + 1 < NKT) {
            loadA((kt + 1) & 1, (kt + 1) * 32);
            loadB((kt + 1) & 1, (kt + 1) * 32);
            asm volatile("cp.async.commit_group;\n");
            asm volatile("cp.async.wait_group 1;\n");
        } else {
            asm volatile("cp.async.wait_group 0;\n");
        }
        __syncthreads();

#pragma unroll
        for (int kk = 0; kk < 32; kk += 16) {
            uint32_t a[4][4];
#pragma unroll
            for (int mi = 0; mi < 4; mi++) {
                int mrow = wm * 64 + mi * 16 + (lane & 15);
                uint32_t addr = (uint32_t)__cvta_generic_to_shared(
                    &As[s][mrow][kk + ((lane >> 4) << 3)]);
                LDSM_X4(a[mi], addr);
            }
#pragma unroll
            for (int ni = 0; ni < 4; ni++) {
                int r = kk + (lane & 15);
                int c0 = (wn * 4 + ni) ^ (r & 7);   // un-swizzle
                uint32_t bb[2];
                uint32_t addr = (uint32_t)__cvta_generic_to_shared(&Bs[s][r][c0 * 8]);
                LDSM_X2T(bb, addr);
#pragma unroll
                for (int mi = 0; mi < 4; mi++) MMA16816(acc[mi][ni], a[mi], bb);
            }
        }
        __syncthreads();
    }

    // epilogue: + b4[o] + x, fp32
    const float* xb = x + (size_t)b * CCH * (HH * WW);
    float* ob = out + (size_t)b * CCH * (HH * WW);
#pragma unroll
    for (int mi = 0; mi < 4; mi++) {
        int o0 = wm * 64 + mi * 16 + (lane >> 2);
        float bz0 = b4[o0], bz1 = b4[o0 + 8];
#pragma unroll
        for (int ni = 0; ni < 4; ni++) {
            int n = n0 + wn * 32 + ni * 8 + (lane & 3) * 2;
            const float2 xv0 = *(const float2*)(xb + (size_t)o0 * (HH * WW) + n);
            const float2 xv1 = *(const float2*)(xb + (size_t)(o0 + 8) * (HH * WW) + n);
            float2 r0, r1;
            r0.x = acc[mi][ni][0] + bz0 + xv0.x;
            r0.y = acc[mi][ni][1] + bz0 + xv0.y;
            r1.x = acc[mi][ni][2] + bz1 + xv1.x;
            r1.y = acc[mi][ni][3] + bz1 + xv1.y;
            *(float2*)(ob + (size_t)o0 * (HH * WW) + n) = r0;
            *(float2*)(ob + (size_t)(o0 + 8) * (HH * WW) + n) = r1;
        }
    }
}

// ---------- launch ----------
extern "C" void kernel_launch(void* const* d_in, const int* in_sizes, int n_in,
                              void* d_out, int out_size) {
    const float* x  = (const float*)d_in[0];
    const float* w1 = (const float*)d_in[1];
    const float* b1 = (const float*)d_in[2];
    const float* w2 = (const float*)d_in[3];
    const float* b2 = (const float*)d_in[4];
    const float* w3 = (const float*)d_in[5];
    const float* b3 = (const float*)d_in[6];
    const float* w4 = (const float*)d_in[7];
    const float* b4 = (const float*)d_in[8];
    float* out = (float*)d_out;

    prep_kernel<<<64, 256>>>(w1, b1, w2, b2, w3, b3, w4);
    dw_kernel<<<dim3(16, 64, NB), 256>>>(x);
    gemm_kernel<<<dim3(128, NB), 256>>>(x, b4, out);
}

// round 16
// speedup vs baseline: 1.0593x; 1.0462x over previous
#include <cuda_runtime.h>
#include <cuda_fp16.h>
#include <cstdint>
#include <cstddef>

#define HH 128
#define WW 128
#define CCH 128
#define NB 8
#define C5T 640

typedef unsigned long long u64;

// ---------- scratch (__device__ globals: allocation-free) ----------
__device__ __half g_y[(size_t)NB * C5T * HH * WW];   // depthwise output (fp16), [b][q][n]
__device__ __half g_w4h[CCH * C5T];                  // w4 fp16, [o=128][q=640]
__device__ float2 g_wtab[64 * 85];                   // [cpair][cell*5+k] folded dw weights
__device__ float  g_bias3[C5T];                      // b1+b2+b3

// ---------- packed f32x2 helpers ----------
__device__ __forceinline__ u64 pack2(float x, float y) {
    u64 p; asm("mov.b64 %0, {%1, %2};" : "=l"(p) : "f"(x), "f"(y)); return p;
}
__device__ __forceinline__ void unpack2(u64 p, float& x, float& y) {
    asm("mov.b64 {%0, %1}, %2;" : "=f"(x), "=f"(y) : "l"(p));
}
__device__ __forceinline__ u64 ffma2(u64 a, u64 b, u64 c) {
    u64 d; asm("fma.rn.f32x2 %0, %1, %2, %3;" : "=l"(d) : "l"(a), "l"(b), "l"(c)); return d;
}
__device__ __forceinline__ u64 fadd2(u64 a, u64 b) {
    u64 d; asm("add.rn.f32x2 %0, %1, %2;" : "=l"(d) : "l"(a), "l"(b)); return d;
}

// ---------- prep: fold weights ----------
__global__ void prep_kernel(const float* __restrict__ w1, const float* __restrict__ b1,
                            const float* __restrict__ w2, const float* __restrict__ b2,
                            const float* __restrict__ w3, const float* __restrict__ b3,
                            const float* __restrict__ w4) {
    int stride = gridDim.x * blockDim.x;
    int tid = blockIdx.x * blockDim.x + threadIdx.x;
    for (int i = tid; i < CCH * C5T; i += stride) g_w4h[i] = __float2half(w4[i]);
    for (int q = tid; q < C5T; q += stride) g_bias3[q] = b1[q] + b2[q] + b3[q];
    const int NC[8] = {0,1,2,3,5,6,7,8};   // 3x3 taps excluding center
    for (int e = tid; e < 64 * 85; e += stride) {
        int cp = e / 85, rem = e % 85, cell = rem / 5, k = rem % 5;
        int q0 = k * CCH + cp * 2;
        float2 wv;
        if (cell == 0) {            // merged center: w1 + center of w2 + center of w3
            wv.x = w1[q0]     + w2[q0*9 + 4]     + w3[q0*9 + 4];
            wv.y = w1[q0 + 1] + w2[(q0+1)*9 + 4] + w3[(q0+1)*9 + 4];
        } else if (cell <= 8) {     // dil-8 taps
            int m = NC[cell - 1];
            wv.x = w2[q0*9 + m]; wv.y = w2[(q0+1)*9 + m];
        } else {                    // dil-12 taps
            int m = NC[cell - 9];
            wv.x = w3[q0*9 + m]; wv.y = w3[(q0+1)*9 + m];
        }
        g_wtab[e] = wv;
    }
}

// ---------- depthwise stencil (f32x2 packed, branch-free masks) ----------
// CTA: 32x32 spatial tile, one channel-pair, batch b. 256 threads:
// col = tid&31, 4 consecutive rows per thread. smem: padded x tile, halo 13.
// Column conv-mask: weight zeroing (branch-free; smem indices always in-bounds).
// Row conv-mask: predicated FFMA (no loads under the predicate).
__global__ __launch_bounds__(256, 2) void dw_kernel(const float* __restrict__ x) {
    __shared__ u64 sx[58][58];
    __shared__ u64 sw[85];
    __shared__ u64 sb[5];

    int b  = blockIdx.z;
    int cp = blockIdx.y;
    int i0 = (blockIdx.x >> 2) * 32;
    int j0 = (blockIdx.x & 3) * 32;
    int tid = threadIdx.x;

    const float* x0 = x + ((size_t)b * CCH + 2 * cp) * (HH * WW);
    const float* x1 = x0 + HH * WW;

    for (int idx = tid; idx < 58 * 58; idx += 256) {
        int sr = idx / 58, sc = idx % 58;
        int gi = i0 - 13 + sr, gj = j0 - 13 + sc;
        float vx = 0.f, vy = 0.f;
        if (gi >= 0 && gi < HH && gj >= 0 && gj < WW) {
            vx = __ldg(x0 + gi * WW + gj);
            vy = __ldg(x1 + gi * WW + gj);
        }
        sx[sr][sc] = pack2(vx, vy);
    }
    if (tid < 85) {
        float2 w = g_wtab[cp * 85 + tid];
        sw[tid] = pack2(w.x, w.y);
    }
    if (tid < 5)
        sb[tid] = pack2(g_bias3[tid * CCH + 2 * cp], g_bias3[tid * CCH + 2 * cp + 1]);
    __syncthreads();

    int col = tid & 31;
    int rt  = (tid >> 5) * 4;     // local row base
    int gj  = j0 + col;
    int gi0 = i0 + rt;

    u64 acc[5][4];
#pragma unroll
    for (int k = 0; k < 5; k++)
#pragma unroll
        for (int p = 0; p < 4; p++) acc[k][p] = 0ull;

    const int OY[17] = {0, -8,-8,-8, 0,0, 8,8,8, -12,-12,-12, 0,0, 12,12,12};
    const int OX[17] = {0, -8,0,8, -8,8, -8,0,8, -12,0,12, -12,12, -12,0,12};

#pragma unroll
    for (int cell = 0; cell < 17; cell++) {
        int gcj = gj + OX[cell];
        bool okc = (gcj >= 0) && (gcj < WW);      // conv-position column mask
        int cc = col + OX[cell] + 13;             // always in [1,56]
        int rr = rt + OY[cell] + 13;              // always in [1,53]
        // branch-free: zero the weights for masked columns
        u64 w0 = okc ? sw[cell*5+0] : 0ull;
        u64 w1 = okc ? sw[cell*5+1] : 0ull;
        u64 w2 = okc ? sw[cell*5+2] : 0ull;
        u64 w3 = okc ? sw[cell*5+3] : 0ull;
        u64 w4 = okc ? sw[cell*5+4] : 0ull;

        u64 strip[6], lft[4], rgt[4];
#pragma unroll
        for (int s = 0; s < 6; s++) strip[s] = sx[rr - 1 + s][cc];
#pragma unroll
        for (int s = 0; s < 4; s++) { lft[s] = sx[rr + s][cc - 1]; rgt[s] = sx[rr + s][cc + 1]; }

#pragma unroll
        for (int p = 0; p < 4; p++) {
            int gci = gi0 + p + OY[cell];
            if (gci >= 0 && gci < HH) {           // row mask: pure-FFMA body -> predication
                acc[0][p] = ffma2(w0, strip[p + 2], acc[0][p]);  // below  (i+1,j)
                acc[1][p] = ffma2(w1, strip[p],     acc[1][p]);  // above  (i-1,j)
                acc[2][p] = ffma2(w2, rgt[p],       acc[2][p]);  // right  (i,j+1)
                acc[3][p] = ffma2(w3, lft[p],       acc[3][p]);  // left   (i,j-1)
                acc[4][p] = ffma2(w4, strip[p + 1], acc[4][p]);  // center (i,j)
            }
        }
    }

    __half* yb = g_y + (size_t)b * C5T * (HH * WW);
#pragma unroll
    for (int k = 0; k < 5; k++) {
#pragma unroll
        for (int p = 0; p < 4; p++) {
            u64 r = fadd2(acc[k][p], sb[k]);
            float rx, ry; unpack2(r, rx, ry);
            size_t n = (size_t)(gi0 + p) * WW + gj;
            yb[(size_t)(k * CCH + 2 * cp) * (HH * WW) + n]     = __float2half(rx);
            yb[(size_t)(k * CCH + 2 * cp + 1) * (HH * WW) + n] = __float2half(ry);
        }
    }
}

// ---------- GEMM: out[b][o][n] = sum_q w4[o][q]*y[b][q][n] + b4[o] + x[b][o][n] ----------
// CTA 128x128, BK=32, 8 warps (2x4), warp 64x32 = 4x4 mma.m16n8k16.
// 3-stage cp.async pipeline; Bs XOR-swizzled for conflict-free ldmatrix.trans.
#define CP16(dst, src) asm volatile("cp.async.cg.shared.global [%0], [%1], 16;\n" :: "r"(dst), "l"(src))
#define LDSM_X4(R, addr) asm volatile("ldmatrix.sync.aligned.m8n8.x4.shared.b16 {%0,%1,%2,%3}, [%4];\n" \
    : "=r"((R)[0]), "=r"((R)[1]), "=r"((R)[2]), "=r"((R)[3]) : "r"(addr))
#define LDSM_X2T(R, addr) asm volatile("ldmatrix.sync.aligned.m8n8.x2.trans.shared.b16 {%0,%1}, [%2];\n" \
    : "=r"((R)[0]), "=r"((R)[1]) : "r"(addr))
#define MMA16816(D, A, B) asm volatile( \
    "mma.sync.aligned.m16n8k16.row.col.f32.f16.f16.f32 {%0,%1,%2,%3},{%4,%5,%6,%7},{%8,%9},{%0,%1,%2,%3};\n" \
    : "+f"((D)[0]), "+f"((D)[1]), "+f"((D)[2]), "+f"((D)[3]) \
    : "r"((A)[0]), "r"((A)[1]), "r"((A)[2]), "r"((A)[3]), "r"((B)[0]), "r"((B)[1]))

__global__ __launch_bounds__(256, 2) void gemm_kernel(const float* __restrict__ x,
                                                      const float* __restrict__ b4,
                                                      float* __restrict__ out) {
    __shared__ __align__(16) __half As[3][128][40];   // [stage][m][k], pad 8: conflict-free
    __shared__ __align__(16) __half Bs[3][32][128];   // [stage][k][n], XOR chunk swizzle

    int b  = blockIdx.y;
    int n0 = blockIdx.x * 128;
    int tid = threadIdx.x;
    const __half* yb = g_y + (size_t)b * C5T * (HH * WW);

    auto loadAB = [&](int s, int k0) {
#pragma unroll
        for (int u = 0; u < 2; u++) {                // A: 512 x 16B
            int ch = tid + 256 * u;
            int row = ch >> 2, kc = (ch & 3) * 8;
            uint32_t dst = (uint32_t)__cvta_generic_to_shared(&As[s][row][kc]);
            CP16(dst, g_w4h + row * C5T + k0 + kc);
        }
#pragma unroll
        for (int u = 0; u < 2; u++) {                // B: 512 x 16B
            int ch = tid + 256 * u;
            int row = ch >> 4, c = ch & 15;
            int sc = c ^ (row & 7);                  // XOR chunk swizzle
            uint32_t dst = (uint32_t)__cvta_generic_to_shared(&Bs[s][row][sc * 8]);
            CP16(dst, yb + (size_t)(k0 + row) * (HH * WW) + n0 + c * 8);
        }
        asm volatile("cp.async.commit_group;\n");
    };

    const int NKT = C5T / 32;   // 20
    loadAB(0, 0);
    loadAB(1, 32);

    float acc[4][4][4];
#pragma unroll
    for (int mi = 0; mi < 4; mi++)
#pragma unroll
        for (int ni = 0; ni < 4; ni++)
#pragma unroll
            for (int r = 0; r < 4; r++) acc[mi][ni][r] = 0.f;

    int wid = tid >> 5, lane = tid & 31;
    int wm = wid >> 2;        // 0..1
    int wn = wid & 3;         // 0..3

    for (int kt = 0; kt < NKT; kt++) {
        int s = kt % 3;
        if (kt + 2 < NKT) {
            loadAB((kt + 2) % 3, (kt + 2) * 32);
            asm volatile("cp.async.wait_group 2;\n");
        } else if (kt + 1 < NKT) {
            asm volatile("cp.async.wait_group 1;\n");
        } else {
            asm volatile("cp.async.wait_group 0;\n");
        }
        __syncthreads();

#pragma unroll
        for (int kk = 0; kk < 32; kk += 16) {
            uint32_t a[4][4];
#pragma unroll
            for (int mi = 0; mi < 4; mi++) {
                int mrow = wm * 64 + mi * 16 + (lane & 15);
                uint32_t addr = (uint32_t)__cvta_generic_to_shared(
                    &As[s][mrow][kk + ((lane >> 4) << 3)]);
                LDSM_X4(a[mi], addr);
            }
#pragma unroll
            for (int ni = 0; ni < 4; ni++) {
                int r = kk + (lane & 15);
                int c0 = (wn * 4 + ni) ^ (r & 7);   // un-swizzle
                uint32_t bb[2];
                uint32_t addr = (uint32_t)__cvta_generic_to_shared(&Bs[s][r][c0 * 8]);
                LDSM_X2T(bb, addr);
#pragma unroll
                for (int mi = 0; mi < 4; mi++) MMA16816(acc[mi][ni], a[mi], bb);
            }
        }
        __syncthreads();
    }

    // epilogue: + b4[o] + x, fp32
    const float* xb = x + (size_t)b * CCH * (HH * WW);
    float* ob = out + (size_t)b * CCH * (HH * WW);
#pragma unroll
    for (int mi = 0; mi < 4; mi++) {
        int o0 = wm * 64 + mi * 16 + (lane >> 2);
        float bz0 = b4[o0], bz1 = b4[o0 + 8];
#pragma unroll
        for (int ni = 0; ni < 4; ni++) {
            int n = n0 + wn * 32 + ni * 8 + (lane & 3) * 2;
            const float2 xv0 = *(const float2*)(xb + (size_t)o0 * (HH * WW) + n);
            const float2 xv1 = *(const float2*)(xb + (size_t)(o0 + 8) * (HH * WW) + n);
            float2 r0, r1;
            r0.x = acc[mi][ni][0] + bz0 + xv0.x;
            r0.y = acc[mi][ni][1] + bz0 + xv0.y;
            r1.x = acc[mi][ni][2] + bz1 + xv1.x;
            r1.y = acc[mi][ni][3] + bz1 + xv1.y;
            *(float2*)(ob + (size_t)o0 * (HH * WW) + n) = r0;
            *(float2*)(ob + (size_t)(o0 + 8) * (HH * WW) + n) = r1;
        }
    }
}

// ---------- launch ----------
extern "C" void kernel_launch(void* const* d_in, const int* in_sizes, int n_in,
                              void* d_out, int out_size) {
    const float* x  = (const float*)d_in[0];
    const float* w1 = (const float*)d_in[1];
    const float* b1 = (const float*)d_in[2];
    const float* w2 = (const float*)d_in[3];
    const float* b2 = (const float*)d_in[4];
    const float* w3 = (const float*)d_in[5];
    const float* b3 = (const float*)d_in[6];
    const float* w4 = (const float*)d_in[7];
    const float* b4 = (const float*)d_in[8];
    float* out = (float*)d_out;

    prep_kernel<<<64, 256>>>(w1, b1, w2, b2, w3, b3, w4);
    dw_kernel<<<dim3(16, 64, NB), 256>>>(x);
    gemm_kernel<<<dim3(128, NB), 256>>>(x, b4, out);
}

// round 17
// speedup vs baseline: 1.0598x; 1.0005x over previous
#include <cuda_runtime.h>
#include <cuda_fp16.h>
#include <cstdint>
#include <cstddef>

#define HH 128
#define WW 128
#define CCH 128
#define NB 8
#define C5T 640

typedef unsigned long long u64;

// ---------- scratch (__device__ globals: allocation-free) ----------
__device__ __half g_y[(size_t)NB * C5T * HH * WW];   // depthwise output (fp16), [b][q][n]
__device__ __half g_w4h[CCH * C5T];                  // w4 fp16, [o=128][q=640]
__device__ float2 g_wtab[64 * 85];                   // [cpair][cell*5+k] folded dw weights
__device__ float  g_bias3[C5T];                      // b1+b2+b3

// ---------- packed f32x2 helpers ----------
__device__ __forceinline__ u64 pack2(float x, float y) {
    u64 p; asm("mov.b64 %0, {%1, %2};" : "=l"(p) : "f"(x), "f"(y)); return p;
}
__device__ __forceinline__ void unpack2(u64 p, float& x, float& y) {
    asm("mov.b64 {%0, %1}, %2;" : "=f"(x), "=f"(y) : "l"(p));
}
__device__ __forceinline__ u64 ffma2(u64 a, u64 b, u64 c) {
    u64 d; asm("fma.rn.f32x2 %0, %1, %2, %3;" : "=l"(d) : "l"(a), "l"(b), "l"(c)); return d;
}
__device__ __forceinline__ u64 fadd2(u64 a, u64 b) {
    u64 d; asm("add.rn.f32x2 %0, %1, %2;" : "=l"(d) : "l"(a), "l"(b)); return d;
}

// ---------- prep: fold weights ----------
__global__ void prep_kernel(const float* __restrict__ w1, const float* __restrict__ b1,
                            const float* __restrict__ w2, const float* __restrict__ b2,
                            const float* __restrict__ w3, const float* __restrict__ b3,
                            const float* __restrict__ w4) {
    int stride = gridDim.x * blockDim.x;
    int tid = blockIdx.x * blockDim.x + threadIdx.x;
    for (int i = tid; i < CCH * C5T; i += stride) g_w4h[i] = __float2half(w4[i]);
    for (int q = tid; q < C5T; q += stride) g_bias3[q] = b1[q] + b2[q] + b3[q];
    const int NC[8] = {0,1,2,3,5,6,7,8};   // 3x3 taps excluding center
    for (int e = tid; e < 64 * 85; e += stride) {
        int cp = e / 85, rem = e % 85, cell = rem / 5, k = rem % 5;
        int q0 = k * CCH + cp * 2;
        float2 wv;
        if (cell == 0) {            // merged center: w1 + center of w2 + center of w3
            wv.x = w1[q0]     + w2[q0*9 + 4]     + w3[q0*9 + 4];
            wv.y = w1[q0 + 1] + w2[(q0+1)*9 + 4] + w3[(q0+1)*9 + 4];
        } else if (cell <= 8) {     // dil-8 taps
            int m = NC[cell - 1];
            wv.x = w2[q0*9 + m]; wv.y = w2[(q0+1)*9 + m];
        } else {                    // dil-12 taps
            int m = NC[cell - 9];
            wv.x = w3[q0*9 + m]; wv.y = w3[(q0+1)*9 + m];
        }
        g_wtab[e] = wv;
    }
}

// ---------- depthwise stencil (f32x2 packed, branch-free masks) ----------
// CTA: 32x32 spatial tile, one channel-pair, batch b. 256 threads:
// col = tid&31, 4 consecutive rows per thread. smem: padded x tile, halo 13.
// Column conv-mask: weight zeroing (branch-free; smem indices always in-bounds).
// Row conv-mask: predicated FFMA (no loads under the predicate).
__global__ __launch_bounds__(256, 2) void dw_kernel(const float* __restrict__ x) {
    __shared__ u64 sx[58][58];
    __shared__ u64 sw[85];
    __shared__ u64 sb[5];

    int b  = blockIdx.z;
    int cp = blockIdx.y;
    int i0 = (blockIdx.x >> 2) * 32;
    int j0 = (blockIdx.x & 3) * 32;
    int tid = threadIdx.x;

    const float* x0 = x + ((size_t)b * CCH + 2 * cp) * (HH * WW);
    const float* x1 = x0 + HH * WW;

    for (int idx = tid; idx < 58 * 58; idx += 256) {
        int sr = idx / 58, sc = idx % 58;
        int gi = i0 - 13 + sr, gj = j0 - 13 + sc;
        float vx = 0.f, vy = 0.f;
        if (gi >= 0 && gi < HH && gj >= 0 && gj < WW) {
            vx = __ldg(x0 + gi * WW + gj);
            vy = __ldg(x1 + gi * WW + gj);
        }
        sx[sr][sc] = pack2(vx, vy);
    }
    if (tid < 85) {
        float2 w = g_wtab[cp * 85 + tid];
        sw[tid] = pack2(w.x, w.y);
    }
    if (tid < 5)
        sb[tid] = pack2(g_bias3[tid * CCH + 2 * cp], g_bias3[tid * CCH + 2 * cp + 1]);
    __syncthreads();

    int col = tid & 31;
    int rt  = (tid >> 5) * 4;     // local row base
    int gj  = j0 + col;
    int gi0 = i0 + rt;

    u64 acc[5][4];
#pragma unroll
    for (int k = 0; k < 5; k++)
#pragma unroll
        for (int p = 0; p < 4; p++) acc[k][p] = 0ull;

    const int OY[17] = {0, -8,-8,-8, 0,0, 8,8,8, -12,-12,-12, 0,0, 12,12,12};
    const int OX[17] = {0, -8,0,8, -8,8, -8,0,8, -12,0,12, -12,12, -12,0,12};

#pragma unroll
    for (int cell = 0; cell < 17; cell++) {
        int gcj = gj + OX[cell];
        bool okc = (gcj >= 0) && (gcj < WW);      // conv-position column mask
        int cc = col + OX[cell] + 13;             // always in [1,56]
        int rr = rt + OY[cell] + 13;              // always in [1,53]
        // branch-free: zero the weights for masked columns
        u64 w0 = okc ? sw[cell*5+0] : 0ull;
        u64 w1 = okc ? sw[cell*5+1] : 0ull;
        u64 w2 = okc ? sw[cell*5+2] : 0ull;
        u64 w3 = okc ? sw[cell*5+3] : 0ull;
        u64 w4 = okc ? sw[cell*5+4] : 0ull;

        u64 strip[6], lft[4], rgt[4];
#pragma unroll
        for (int s = 0; s < 6; s++) strip[s] = sx[rr - 1 + s][cc];
#pragma unroll
        for (int s = 0; s < 4; s++) { lft[s] = sx[rr + s][cc - 1]; rgt[s] = sx[rr + s][cc + 1]; }

#pragma unroll
        for (int p = 0; p < 4; p++) {
            int gci = gi0 + p + OY[cell];
            if (gci >= 0 && gci < HH) {           // row mask: pure-FFMA body -> predication
                acc[0][p] = ffma2(w0, strip[p + 2], acc[0][p]);  // below  (i+1,j)
                acc[1][p] = ffma2(w1, strip[p],     acc[1][p]);  // above  (i-1,j)
                acc[2][p] = ffma2(w2, rgt[p],       acc[2][p]);  // right  (i,j+1)
                acc[3][p] = ffma2(w3, lft[p],       acc[3][p]);  // left   (i,j-1)
                acc[4][p] = ffma2(w4, strip[p + 1], acc[4][p]);  // center (i,j)
            }
        }
    }

    __half* yb = g_y + (size_t)b * C5T * (HH * WW);
#pragma unroll
    for (int k = 0; k < 5; k++) {
#pragma unroll
        for (int p = 0; p < 4; p++) {
            u64 r = fadd2(acc[k][p], sb[k]);
            float rx, ry; unpack2(r, rx, ry);
            size_t n = (size_t)(gi0 + p) * WW + gj;
            yb[(size_t)(k * CCH + 2 * cp) * (HH * WW) + n]     = __float2half(rx);
            yb[(size_t)(k * CCH + 2 * cp + 1) * (HH * WW) + n] = __float2half(ry);
        }
    }
}

// ---------- GEMM: out[b][o][n] = sum_q w4[o][q]*y[b][q][n] + b4[o] + x[b][o][n] ----------
// CTA 128x128, BK=32, 8 warps (2x4), warp 64x32 = 4x4 mma.m16n8k16.
// 3-stage cp.async pipeline; Bs XOR-swizzled for conflict-free ldmatrix.trans.
#define CP16(dst, src) asm volatile("cp.async.cg.shared.global [%0], [%1], 16;\n" :: "r"(dst), "l"(src))
#define LDSM_X4(R, addr) asm volatile("ldmatrix.sync.aligned.m8n8.x4.shared.b16 {%0,%1,%2,%3}, [%4];\n" \
    : "=r"((R)[0]), "=r"((R)[1]), "=r"((R)[2]), "=r"((R)[3]) : "r"(addr))
#define LDSM_X2T(R, addr) asm volatile("ldmatrix.sync.aligned.m8n8.x2.trans.shared.b16 {%0,%1}, [%2];\n" \
    : "=r"((R)[0]), "=r"((R)[1]) : "r"(addr))
#define MMA16816(D, A, B) asm volatile( \
    "mma.sync.aligned.m16n8k16.row.col.f32.f16.f16.f32 {%0,%1,%2,%3},{%4,%5,%6,%7},{%8,%9},{%0,%1,%2,%3};\n" \
    : "+f"((D)[0]), "+f"((D)[1]), "+f"((D)[2]), "+f"((D)[3]) \
    : "r"((A)[0]), "r"((A)[1]), "r"((A)[2]), "r"((A)[3]), "r"((B)[0]), "r"((B)[1]))

__global__ __launch_bounds__(256, 2) void gemm_kernel(const float* __restrict__ x,
                                                      const float* __restrict__ b4,
                                                      float* __restrict__ out) {
    __shared__ __align__(16) __half As[3][128][40];   // [stage][m][k], pad 8: conflict-free
    __shared__ __align__(16) __half Bs[3][32][128];   // [stage][k][n], XOR chunk swizzle

    int b  = blockIdx.y;
    int n0 = blockIdx.x * 128;
    int tid = threadIdx.x;
    const __half* yb = g_y + (size_t)b * C5T * (HH * WW);

    auto loadAB = [&](int s, int k0) {
#pragma unroll
        for (int u = 0; u < 2; u++) {                // A: 512 x 16B
            int ch = tid + 256 * u;
            int row = ch >> 2, kc = (ch & 3) * 8;
            uint32_t dst = (uint32_t)__cvta_generic_to_shared(&As[s][row][kc]);
            CP16(dst, g_w4h + row * C5T + k0 + kc);
        }
#pragma unroll
        for (int u = 0; u < 2; u++) {                // B: 512 x 16B
            int ch = tid + 256 * u;
            int row = ch >> 4, c = ch & 15;
            int sc = c ^ (row & 7);                  // XOR chunk swizzle
            uint32_t dst = (uint32_t)__cvta_generic_to_shared(&Bs[s][row][sc * 8]);
            CP16(dst, yb + (size_t)(k0 + row) * (HH * WW) + n0 + c * 8);
        }
        asm volatile("cp.async.commit_group;\n");
    };

    const int NKT = C5T / 32;   // 20
    loadAB(0, 0);
    loadAB(1, 32);

    float acc[4][4][4];
#pragma unroll
    for (int mi = 0; mi < 4; mi++)
#pragma unroll
        for (int ni = 0; ni < 4; ni++)
#pragma unroll
            for (int r = 0; r < 4; r++) acc[mi][ni][r] = 0.f;

    int wid = tid >> 5, lane = tid & 31;
    int wm = wid >> 2;        // 0..1
    int wn = wid & 3;         // 0..3

    for (int kt = 0; kt < NKT; kt++) {
        int s = kt % 3;
        if (kt + 2 < NKT) {
            loadAB((kt + 2) % 3, (kt + 2) * 32);
            asm volatile("cp.async.wait_group 2;\n");
        } else if (kt + 1 < NKT) {
            asm volatile("cp.async.wait_group 1;\n");
        } else {
            asm volatile("cp.async.wait_group 0;\n");
        }
        __syncthreads();

#pragma unroll
        for (int kk = 0; kk < 32; kk += 16) {
            uint32_t a[4][4];
#pragma unroll
            for (int mi = 0; mi < 4; mi++) {
                int mrow = wm * 64 + mi * 16 + (lane & 15);
                uint32_t addr = (uint32_t)__cvta_generic_to_shared(
                    &As[s][mrow][kk + ((lane >> 4) << 3)]);
                LDSM_X4(a[mi], addr);
            }
#pragma unroll
            for (int ni = 0; ni < 4; ni++) {
                int r = kk + (lane & 15);
                int c0 = (wn * 4 + ni) ^ (r & 7);   // un-swizzle
                uint32_t bb[2];
                uint32_t addr = (uint32_t)__cvta_generic_to_shared(&Bs[s][r][c0 * 8]);
                LDSM_X2T(bb, addr);
#pragma unroll
                for (int mi = 0; mi < 4; mi++) MMA16816(acc[mi][ni], a[mi], bb);
            }
        }
        __syncthreads();
    }

    // epilogue: + b4[o] + x, fp32
    const float* xb = x + (size_t)b * CCH * (HH * WW);
    float* ob = out + (size_t)b * CCH * (HH * WW);
#pragma unroll
    for (int mi = 0; mi < 4; mi++) {
        int o0 = wm * 64 + mi * 16 + (lane >> 2);
        float bz0 = b4[o0], bz1 = b4[o0 + 8];
#pragma unroll
        for (int ni = 0; ni < 4; ni++) {
            int n = n0 + wn * 32 + ni * 8 + (lane & 3) * 2;
            const float2 xv0 = *(const float2*)(xb + (size_t)o0 * (HH * WW) + n);
            const float2 xv1 = *(const float2*)(xb + (size_t)(o0 + 8) * (HH * WW) + n);
            float2 r0, r1;
            r0.x = acc[mi][ni][0] + bz0 + xv0.x;
            r0.y = acc[mi][ni][1] + bz0 + xv0.y;
            r1.x = acc[mi][ni][2] + bz1 + xv1.x;
            r1.y = acc[mi][ni][3] + bz1 + xv1.y;
            *(float2*)(ob + (size_t)o0 * (HH * WW) + n) = r0;
            *(float2*)(ob + (size_t)(o0 + 8) * (HH * WW) + n) = r1;
        }
    }
}

// ---------- launch ----------
extern "C" void kernel_launch(void* const* d_in, const int* in_sizes, int n_in,
                              void* d_out, int out_size) {
    const float* x  = (const float*)d_in[0];
    const float* w1 = (const float*)d_in[1];
    const float* b1 = (const float*)d_in[2];
    const float* w2 = (const float*)d_in[3];
    const float* b2 = (const float*)d_in[4];
    const float* w3 = (const float*)d_in[5];
    const float* b3 = (const float*)d_in[6];
    const float* w4 = (const float*)d_in[7];
    const float* b4 = (const float*)d_in[8];
    float* out = (float*)d_out;

    prep_kernel<<<64, 256>>>(w1, b1, w2, b2, w3, b3, w4);
    dw_kernel<<<dim3(16, 64, NB), 256>>>(x);
    gemm_kernel<<<dim3(128, NB), 256>>>(x, b4, out);
}